// round 6
// baseline (speedup 1.0000x reference)
#include <cuda_runtime.h>
#include <cuda_bf16.h>
#include <cstdint>

// Problem constants (shape-specialized)
#define NY 496
#define NX 432
#define NZp 1
#define CCH 64
#define BATCH 4
#define SPATIAL (NY * NX * NZp)          // 214272
#define TOTAL_CELLS (BATCH * SPATIAL)    // 857088
#define CELLS_PER_BLK 64
#define NTILES (TOTAL_CELLS / CELLS_PER_BLK)   // 13392

// Per-cell winner voxel index + 1 (0 = empty). Zero-initialized at module
// load; the gather phase restores every touched entry to 0, so the all-zero
// invariant holds across graph replays. 3.27 MB static scratch — no runtime
// allocation.
__device__ int g_winner[TOTAL_CELLS];

// Non-resetting grid-barrier ticket counter. Monotonically increasing across
// calls/replays: each call's G blocks take tickets in [k*G, (k+1)*G) and wait
// for g_bar to reach (k+1)*G. Deterministic work regardless of k.
__device__ unsigned int g_bar;

// Fused persistent kernel: vote (grid-stride) -> grid barrier -> gather tiles.
// Grid is sized host-side to exactly the co-resident block count, so the
// software barrier cannot deadlock.
__global__ __launch_bounds__(256) void k_fused(const float4* __restrict__ feat4,
                                               const int4*   __restrict__ coors,
                                               int n,
                                               float* __restrict__ out) {
    __shared__ float tile[CELLS_PER_BLK][65];  // stride 65: phase-B <=2-way conflict
    __shared__ int   win[CELLS_PER_BLK];

    const int tid = threadIdx.x;
    const unsigned G = gridDim.x;

    // ---- Phase 1: vote (last-write-wins; atomicMax(i+1) == sequential
    //      .at[].set order since highest index wins) ----
    for (int i = blockIdx.x * 256 + tid; i < n; i += (int)G * 256) {
        int4 c = coors[i];   // [b, z, y, x]
        int g = c.x * SPATIAL + c.z * (NX * NZp) + c.w * NZp + c.y;
        atomicMax(&g_winner[g], i + 1);
    }

    // ---- Grid barrier: release all vote writes, arrive, spin-acquire ----
    __threadfence();
    __syncthreads();
    if (tid == 0) {
        unsigned t = atomicAdd(&g_bar, 1u);
        unsigned target = (t / G + 1u) * G;
        unsigned v;
        do {
            asm volatile("ld.acquire.gpu.u32 %0, [%1];"
                         : "=r"(v) : "l"(&g_bar) : "memory");
        } while (v < target);
    }
    __syncthreads();

    // ---- Phase 2: gather tiles (64 cells x 64 ch), persistent loop ----
    const int v4 = tid & 15;   // float4 index within a 64-ch row
    const int cg = tid >> 4;   // cell-within-pass

    for (int t = blockIdx.x; t < NTILES; t += (int)G) {
        const int cell0 = t * CELLS_PER_BLK;   // SPATIAL % 64 == 0: no batch straddle
        const int b     = cell0 / SPATIAL;
        const int s0    = cell0 - b * SPATIAL;

        __syncthreads();   // protect win[]/tile[] from previous iteration's readers

        int my_w = 0;
        if (tid < CELLS_PER_BLK) {
            my_w = g_winner[cell0 + tid];
            win[tid] = my_w;
        }
        __syncthreads();

        // Phase A: 16 threads/cell LDG.128 the cell's 256B feature row (or 0).
        int w0 = win[cg +  0];
        int w1 = win[cg + 16];
        int w2 = win[cg + 32];
        int w3 = win[cg + 48];
        float4 z  = make_float4(0.f, 0.f, 0.f, 0.f);
        float4 f0 = w0 ? feat4[(size_t)(w0 - 1) * (CCH / 4) + v4] : z;
        float4 f1 = w1 ? feat4[(size_t)(w1 - 1) * (CCH / 4) + v4] : z;
        float4 f2 = w2 ? feat4[(size_t)(w2 - 1) * (CCH / 4) + v4] : z;
        float4 f3 = w3 ? feat4[(size_t)(w3 - 1) * (CCH / 4) + v4] : z;
        if (tid < CELLS_PER_BLK && my_w) g_winner[cell0 + tid] = 0;  // restore invariant

        float* tr;
        tr = &tile[cg +  0][4 * v4]; tr[0] = f0.x; tr[1] = f0.y; tr[2] = f0.z; tr[3] = f0.w;
        tr = &tile[cg + 16][4 * v4]; tr[0] = f1.x; tr[1] = f1.y; tr[2] = f1.z; tr[3] = f1.w;
        tr = &tile[cg + 32][4 * v4]; tr[0] = f2.x; tr[1] = f2.y; tr[2] = f2.z; tr[3] = f2.w;
        tr = &tile[cg + 48][4 * v4]; tr[0] = f3.x; tr[1] = f3.y; tr[2] = f3.z; tr[3] = f3.w;
        __syncthreads();

        // Phase B: transpose out of smem, 128-bit coalesced stores.
        float* ob = out + (size_t)b * CCH * SPATIAL + s0;
#pragma unroll
        for (int q = 0; q < 4; ++q) {
            int i  = q * 256 + tid;
            int cc = i >> 4;            // channel 0..63
            int s  = (i & 15) * 4;      // spatial offset 0..60
            float4 o;
            o.x = tile[s + 0][cc];
            o.y = tile[s + 1][cc];
            o.z = tile[s + 2][cc];
            o.w = tile[s + 3][cc];
            *reinterpret_cast<float4*>(ob + (size_t)cc * SPATIAL + s) = o;
        }
    }
}

extern "C" void kernel_launch(void* const* d_in, const int* in_sizes, int n_in,
                              void* d_out, int out_size) {
    const float4* feat4 = (const float4*)d_in[0];
    const int4*   coors = (const int4*)d_in[1];
    float*        out   = (float*)d_out;

    const int n = in_sizes[0] / CCH;  // 320000

    // Size the grid to exactly the co-resident capacity -> barrier-safe.
    int dev = 0, sms = 0, occ = 0;
    cudaGetDevice(&dev);
    cudaDeviceGetAttribute(&sms, cudaDevAttrMultiProcessorCount, dev);
    cudaOccupancyMaxActiveBlocksPerMultiprocessor(&occ, k_fused, 256, 0);
    int grid = sms * occ;
    if (grid < 1) grid = 1;            // even 1 block completes correctly
    if (grid > NTILES) grid = NTILES;  // never more blocks than tiles

    k_fused<<<grid, 256>>>(feat4, coors, n, out);
}